// round 14
// baseline (speedup 1.0000x reference)
#include <cuda_runtime.h>
#include <cuda_fp16.h>
#include <math.h>
#include <stdint.h>

#define LQ   2048
#define SK   2048
#define NB   4
#define EE   1024
#define FFD  4096
#define MTOK (LQ * NB)

typedef __half  f16;
typedef __half2 f162;

// ---------------------------------------------------------------------------
// Scratch (device globals)
// ---------------------------------------------------------------------------
__device__ f16 s_hh [(size_t)MTOK * EE];          // LN out
__device__ f16 s_qkv[(size_t)MTOK * 3 * EE];      // self q|k|v fused
__device__ f16 s_qh [(size_t)MTOK * EE];          // cross q
__device__ f16 s_kv [(size_t)MTOK * 2 * EE];      // cross k|v fused
__device__ f16 s_ph [(size_t)NB * LQ * SK];       // probs
__device__ f16 s_abh[(size_t)MTOK * EE];          // attn out
__device__ f16 s_ffh[(size_t)MTOK * FFD];         // MLP hidden
__device__ f16 s_mh [(size_t)MTOK * EE];          // memory fp16
__device__ f16 s_w3 [(size_t)3 * EE * EE];        // sa qkv weights
__device__ f16 s_wow[(size_t)EE * EE];            // sa out w
__device__ f16 s_cq [(size_t)EE * EE];            // ca q w
__device__ f16 s_ckv[(size_t)2 * EE * EE];        // ca kv weights
__device__ f16 s_cow[(size_t)EE * EE];            // ca out w
__device__ f16 s_w1 [(size_t)FFD * EE];
__device__ f16 s_w2 [(size_t)FFD * EE];
__device__ float g_s [(size_t)NB * LQ * SK];      // f32 scores

// ---------------------------------------------------------------------------
// Helpers
// ---------------------------------------------------------------------------
__device__ __forceinline__ float warpSum(float v) {
#pragma unroll
    for (int o = 16; o > 0; o >>= 1) v += __shfl_xor_sync(0xffffffffu, v, o);
    return v;
}
__device__ __forceinline__ float warpMax(float v) {
#pragma unroll
    for (int o = 16; o > 0; o >>= 1) v = fmaxf(v, __shfl_xor_sync(0xffffffffu, v, o));
    return v;
}
__device__ __forceinline__ float blockSum(float v, float* sh) {
    int lane = threadIdx.x & 31, wid = threadIdx.x >> 5;
    v = warpSum(v);
    if (lane == 0) sh[wid] = v;
    __syncthreads();
    float r = (lane < 8) ? sh[lane] : 0.f;
    r = warpSum(r);
    __syncthreads();
    return r;
}
__device__ __forceinline__ float blockMax(float v, float* sh) {
    int lane = threadIdx.x & 31, wid = threadIdx.x >> 5;
    v = warpMax(v);
    if (lane == 0) sh[wid] = v;
    __syncthreads();
    float r = (lane < 8) ? sh[lane] : -3.4e38f;
    r = warpMax(r);
    __syncthreads();
    return r;
}

// ---------------------------------------------------------------------------
// PTX wrappers (sm_80-class — compute_103-safe)
// ---------------------------------------------------------------------------
__device__ __forceinline__ void cpa16(uint32_t dst, const void* src) {
    asm volatile("cp.async.cg.shared.global [%0], [%1], 16;" :: "r"(dst), "l"(src));
}
#define CP_COMMIT() asm volatile("cp.async.commit_group;" ::: "memory")
#define CP_WAIT0()  asm volatile("cp.async.wait_group 0;" ::: "memory")
#define CP_WAIT1()  asm volatile("cp.async.wait_group 1;" ::: "memory")

__device__ __forceinline__ void ldsm4(uint32_t* r, uint32_t addr) {
    asm volatile("ldmatrix.sync.aligned.m8n8.x4.shared.b16 {%0,%1,%2,%3}, [%4];"
        : "=r"(r[0]), "=r"(r[1]), "=r"(r[2]), "=r"(r[3]) : "r"(addr));
}
__device__ __forceinline__ void ldsm4t(uint32_t* r, uint32_t addr) {
    asm volatile("ldmatrix.sync.aligned.m8n8.x4.trans.shared.b16 {%0,%1,%2,%3}, [%4];"
        : "=r"(r[0]), "=r"(r[1]), "=r"(r[2]), "=r"(r[3]) : "r"(addr));
}
__device__ __forceinline__ void mma_f16(float* d, const uint32_t* a, const uint32_t* b) {
    asm volatile(
        "mma.sync.aligned.m16n8k16.row.col.f32.f16.f16.f32 "
        "{%0,%1,%2,%3}, {%4,%5,%6,%7}, {%8,%9}, {%0,%1,%2,%3};\n"
        : "+f"(d[0]), "+f"(d[1]), "+f"(d[2]), "+f"(d[3])
        : "r"(a[0]), "r"(a[1]), "r"(a[2]), "r"(a[3]), "r"(b[0]), "r"(b[1]));
}

// ---------------------------------------------------------------------------
// f32 -> fp16 convert
// ---------------------------------------------------------------------------
__global__ void cvt_kernel(const float* __restrict__ x, f16* __restrict__ o,
                           long long n4) {
    long long i = blockIdx.x * (long long)blockDim.x + threadIdx.x;
    if (i >= n4) return;
    float4 v = ((const float4*)x)[i];
    ((f162*)o)[i * 2]     = __halves2half2(__float2half_rn(v.x), __float2half_rn(v.y));
    ((f162*)o)[i * 2 + 1] = __halves2half2(__float2half_rn(v.z), __float2half_rn(v.w));
}

// ---------------------------------------------------------------------------
// LayerNorm -> fp16
// ---------------------------------------------------------------------------
__global__ void ln_kernel(const float* __restrict__ x, const float* __restrict__ g,
                          const float* __restrict__ b, f16* __restrict__ oh) {
    __shared__ float sh[32];
    long long row = blockIdx.x;
    float4 v = ((const float4*)(x + row * EE))[threadIdx.x];
    float s  = v.x + v.y + v.z + v.w;
    float sq = v.x * v.x + v.y * v.y + v.z * v.z + v.w * v.w;
    s  = blockSum(s,  sh);
    sq = blockSum(sq, sh);
    float mean = s * (1.f / EE);
    float var  = sq * (1.f / EE) - mean * mean;
    float inv  = rsqrtf(var + 1e-5f);
    float4 gv = ((const float4*)g)[threadIdx.x];
    float4 bv = ((const float4*)b)[threadIdx.x];
    float o0 = (v.x - mean) * inv * gv.x + bv.x;
    float o1 = (v.y - mean) * inv * gv.y + bv.y;
    float o2 = (v.z - mean) * inv * gv.z + bv.z;
    float o3 = (v.w - mean) * inv * gv.w + bv.w;
    f162* ph = (f162*)(oh + row * EE);
    ph[threadIdx.x * 2]     = __halves2half2(__float2half_rn(o0), __float2half_rn(o1));
    ph[threadIdx.x * 2 + 1] = __halves2half2(__float2half_rn(o2), __float2half_rn(o3));
}

// ---------------------------------------------------------------------------
// Softmax over S=2048 -> fp16 probs; mask-select (skipped tiles never read).
// Causal rows skip loading the second half when fully masked.
// ---------------------------------------------------------------------------
__global__ void softmax_kernel(const float* __restrict__ s, const float* __restrict__ mask,
                               f16* __restrict__ oh) {
    __shared__ float sh[32];
    long long row = blockIdx.x;
    int l = (int)(row & (LQ - 1));
    const float4* sr = (const float4*)(s + row * (long long)SK);
    float4 va = sr[threadIdx.x];
    float4 vb;
    bool need_b = !mask || (1024 + (int)threadIdx.x * 4 <= l);
    if (need_b) vb = sr[threadIdx.x + 256];
    else        vb = make_float4(-3.0e38f, -3.0e38f, -3.0e38f, -3.0e38f);
    if (mask) {
        const float4* mr = (const float4*)(mask + (long long)l * SK);
        float4 ma = mr[threadIdx.x];
        va.x = (ma.x < -1e8f) ? -3.0e38f : va.x;
        va.y = (ma.y < -1e8f) ? -3.0e38f : va.y;
        va.z = (ma.z < -1e8f) ? -3.0e38f : va.z;
        va.w = (ma.w < -1e8f) ? -3.0e38f : va.w;
        if (need_b) {
            float4 mb = mr[threadIdx.x + 256];
            vb.x = (mb.x < -1e8f) ? -3.0e38f : vb.x;
            vb.y = (mb.y < -1e8f) ? -3.0e38f : vb.y;
            vb.z = (mb.z < -1e8f) ? -3.0e38f : vb.z;
            vb.w = (mb.w < -1e8f) ? -3.0e38f : vb.w;
        }
    }
    float mx = fmaxf(fmaxf(fmaxf(va.x, va.y), fmaxf(va.z, va.w)),
                     fmaxf(fmaxf(vb.x, vb.y), fmaxf(vb.z, vb.w)));
    mx = blockMax(mx, sh);
    va.x = __expf(va.x - mx); va.y = __expf(va.y - mx);
    va.z = __expf(va.z - mx); va.w = __expf(va.w - mx);
    vb.x = __expf(vb.x - mx); vb.y = __expf(vb.y - mx);
    vb.z = __expf(vb.z - mx); vb.w = __expf(vb.w - mx);
    float sum = va.x + va.y + va.z + va.w + vb.x + vb.y + vb.z + vb.w;
    sum = blockSum(sum, sh);
    float inv = 1.f / sum;
    f162* ph = (f162*)(oh + row * (long long)SK);
    ph[threadIdx.x * 2] = __halves2half2(__float2half_rn(va.x * inv), __float2half_rn(va.y * inv));
    ph[threadIdx.x * 2 + 1] = __halves2half2(__float2half_rn(va.z * inv), __float2half_rn(va.w * inv));
    ph[(threadIdx.x + 256) * 2] = __halves2half2(__float2half_rn(vb.x * inv), __float2half_rn(vb.y * inv));
    ph[(threadIdx.x + 256) * 2 + 1] = __halves2half2(__float2half_rn(vb.z * inv), __float2half_rn(vb.w * inv));
}

// ---------------------------------------------------------------------------
// Tensor-core GEMM, single-term fp16: C = epi(A @ op(B)).
// 128x256 CTA tile, BK=32, 256 threads (2x4 warps), 64x64 warp tile.
// 3-stage cp.async pipeline, 1 CTA/SM (high reg count), 4:1 MMA:ldsm ratio.
// TRANSB=1: B [N,K] row-major. TRANSB=0: B [K,N].
// ACT: 0 none, 1 QuickGELU, 2 = alpha applied only to cols < EE (fused QKV).
// OUT: 0 = f32 (+res), 3 = fp16.
// CAUSAL: 0 none, 1 = K truncated at bm+128 (P@V, LPT-reversed bm order),
//         2 = skip tiles bn >= bm+128.
// smem/stage: A 128x80B = 10240, B 256x80B (or 32x528B) = 20480 -> 30720.
// ---------------------------------------------------------------------------
#define B_OFF  10240u
#define STAGE  30720u
#define SMEMSZ (3u * STAGE)

template <int TRANSB, int ACT, int OUT, int CAUSAL>
__global__ void __launch_bounds__(256, 1)
gemm_tc(const f16* __restrict__ Ah, const f16* __restrict__ Bh,
        const float* __restrict__ bias, const float* __restrict__ res,
        float* C, f16* Ch,
        int K, int lda, int ldb, int ldc,
        long long sA, long long sB, long long sC, float alpha) {
    // LPT: for variable-K causal P@V, schedule longest-K CTAs first.
    const int ytile = (CAUSAL == 1) ? (gridDim.y - 1 - blockIdx.y) : blockIdx.y;
    const int bm = ytile * 128;
    const int bn = blockIdx.x * 256;
    if (CAUSAL == 2 && bn >= bm + 128) return;  // fully-masked score tile

    Ah += (long long)blockIdx.z * sA;
    Bh += (long long)blockIdx.z * sB;
    if (OUT == 0) { C  += (long long)blockIdx.z * sC; if (res) res += (long long)blockIdx.z * sC; }
    else          { Ch += (long long)blockIdx.z * sC; }

    extern __shared__ f16 smem[];
    const uint32_t sbase = (uint32_t)__cvta_generic_to_shared(smem);
    const int tid  = threadIdx.x;
    const int lane = tid & 31;
    const int warp = tid >> 5;
    const int wm = warp >> 2;   // 0..1  (row 64-block)
    const int wn = warp & 3;    // 0..3  (col 64-block)

    float acc[4][8][4];
#pragma unroll
    for (int i = 0; i < 4; i++)
#pragma unroll
        for (int j = 0; j < 8; j++)
#pragma unroll
            for (int q = 0; q < 4; q++) acc[i][j][q] = 0.f;

    auto load_stage = [&](int st, int k0) {
        uint32_t sb = sbase + (uint32_t)st * STAGE;
#pragma unroll
        for (int i = 0; i < 2; i++) {               // A: 128 rows x 4 16B chunks
            int c = tid + i * 256;
            int row = c >> 2, kc = c & 3;
            size_t off = (size_t)(bm + row) * lda + k0 + kc * 8;
            cpa16(sb + row * 80 + kc * 16, Ah + off);
        }
        if (TRANSB) {
#pragma unroll
            for (int i = 0; i < 4; i++) {           // B: 256 rows x 4 chunks
                int c = tid + i * 256;
                int row = c >> 2, kc = c & 3;
                size_t off = (size_t)(bn + row) * ldb + k0 + kc * 8;
                cpa16(sb + B_OFF + row * 80 + kc * 16, Bh + off);
            }
        } else {
#pragma unroll
            for (int i = 0; i < 4; i++) {           // B: 32 k-rows x 32 chunks
                int c = tid + i * 256;
                int row = c >> 5, nc = c & 31;
                size_t off = (size_t)(k0 + row) * ldb + bn + nc * 8;
                cpa16(sb + B_OFF + row * 528 + nc * 16, Bh + off);
            }
        }
        CP_COMMIT();
    };

    auto compute_stage = [&](int st) {
        uint32_t sA_ = sbase + (uint32_t)st * STAGE;
        uint32_t sB_ = sA_ + B_OFF;
#pragma unroll
        for (int ks = 0; ks < 2; ks++) {
            const int k16 = ks * 16;
            uint32_t ah[4][4], bh[8][2];
            const int arow = lane & 15;
            const int acol = k16 + (lane >> 4) * 8;
#pragma unroll
            for (int mt = 0; mt < 4; mt++) {
                uint32_t addr = sA_ + (uint32_t)((wm * 64 + mt * 16 + arow) * 80 + acol * 2);
                ldsm4(ah[mt], addr);
            }
            if (TRANSB) {
                // rows = n, 16 rows per ldsm4; r0,r2 = frag n..n+7; r1,r3 = n+8..n+15
#pragma unroll
                for (int nt2 = 0; nt2 < 4; nt2++) {
                    uint32_t r[4];
                    uint32_t addr = sB_ + (uint32_t)((wn * 64 + nt2 * 16 + arow) * 80 + acol * 2);
                    ldsm4(r, addr);
                    bh[2 * nt2][0]     = r[0]; bh[2 * nt2][1]     = r[2];
                    bh[2 * nt2 + 1][0] = r[1]; bh[2 * nt2 + 1][1] = r[3];
                }
            } else {
                // rows = k (trans); r0,r1 = frag n..n+7; r2,r3 = n+8..n+15
                const int krow = k16 + ((lane >> 3) & 1) * 8 + (lane & 7);
                const int ng = ((lane >> 4) & 1) * 8;
#pragma unroll
                for (int nt2 = 0; nt2 < 4; nt2++) {
                    uint32_t r[4];
                    const int ncol = wn * 64 + nt2 * 16 + ng;
                    uint32_t addr = sB_ + (uint32_t)(krow * 528 + ncol * 2);
                    ldsm4t(r, addr);
                    bh[2 * nt2][0]     = r[0]; bh[2 * nt2][1]     = r[1];
                    bh[2 * nt2 + 1][0] = r[2]; bh[2 * nt2 + 1][1] = r[3];
                }
            }
#pragma unroll
            for (int mt = 0; mt < 4; mt++)
#pragma unroll
                for (int nt = 0; nt < 8; nt++)
                    mma_f16(acc[mt][nt], ah[mt], bh[nt]);
        }
    };

    const int Kend = (CAUSAL == 1) ? min(K, bm + 128) : K;
    const int KT = Kend >> 5;
    load_stage(0, 0);
    if (KT > 1) load_stage(1, 32);
    for (int kt = 0; kt < KT; kt++) {
        if (kt + 1 < KT) CP_WAIT1(); else CP_WAIT0();
        __syncthreads();
        if (kt + 2 < KT) load_stage((kt + 2) % 3, (kt + 2) * 32);
        compute_stage(kt % 3);
    }

    // Epilogue
#pragma unroll
    for (int mt = 0; mt < 4; mt++) {
        const int r0 = bm + wm * 64 + mt * 16 + (lane >> 2);
#pragma unroll
        for (int nt = 0; nt < 8; nt++) {
            const int c = bn + wn * 64 + nt * 8 + (lane & 3) * 2;
            float bc0 = 0.f, bc1 = 0.f;
            if (bias) { bc0 = bias[c]; bc1 = bias[c + 1]; }
            const float af = (ACT == 2) ? ((c < EE) ? alpha : 1.f) : alpha;
#pragma unroll
            for (int h = 0; h < 2; h++) {
                float v0 = acc[mt][nt][h * 2 + 0] + bc0;
                float v1 = acc[mt][nt][h * 2 + 1] + bc1;
                v0 *= af; v1 *= af;
                if (ACT == 1) {
                    v0 = v0 / (1.f + __expf(-1.702f * v0));
                    v1 = v1 / (1.f + __expf(-1.702f * v1));
                }
                const size_t row = (size_t)(r0 + h * 8);
                if (OUT == 0) {
                    if (res) {
                        const float2 rv = *(const float2*)(res + row * ldc + c);
                        v0 += rv.x; v1 += rv.y;
                    }
                    *(float2*)(C + row * ldc + c) = make_float2(v0, v1);
                } else {
                    *(f162*)(Ch + row * ldc + c) =
                        __halves2half2(__float2half_rn(v0), __float2half_rn(v1));
                }
            }
        }
    }
}

// ---------------------------------------------------------------------------
// Host launcher — R13 dual-stream fork-join topology (known-good)
// ---------------------------------------------------------------------------
extern "C" void kernel_launch(void* const* d_in, const int* in_sizes, int n_in,
                              void* d_out, int out_size) {
    const float* tgt    = (const float*)d_in[0];
    const float* memory = (const float*)d_in[1];
    const float* mask   = (const float*)d_in[2];
    const float* sa_qw  = (const float*)d_in[3];
    const float* sa_kw  = (const float*)d_in[4];
    const float* sa_vw  = (const float*)d_in[5];
    const float* sa_b   = (const float*)d_in[6];
    const float* sa_ow  = (const float*)d_in[7];
    const float* sa_ob  = (const float*)d_in[8];
    const float* ca_qw  = (const float*)d_in[9];
    const float* ca_kw  = (const float*)d_in[10];
    const float* ca_vw  = (const float*)d_in[11];
    const float* ca_b   = (const float*)d_in[12];
    const float* ca_ow  = (const float*)d_in[13];
    const float* ca_ob  = (const float*)d_in[14];
    const float* ln1_g  = (const float*)d_in[15];
    const float* ln1_b  = (const float*)d_in[16];
    const float* ln2_g  = (const float*)d_in[17];
    const float* ln2_b  = (const float*)d_in[18];
    const float* ln3_g  = (const float*)d_in[19];
    const float* ln3_b  = (const float*)d_in[20];
    const float* w1     = (const float*)d_in[21];
    const float* b1     = (const float*)d_in[22];
    const float* w2     = (const float*)d_in[23];
    const float* b2     = (const float*)d_in[24];
    float* x = (float*)d_out;

    f16 *hh, *qkv, *qh, *kv, *ph, *abh, *ffh, *mh, *w3, *wow, *cq, *ckv, *cow, *wf1, *wf2;
    float* sb;
    cudaGetSymbolAddress((void**)&hh,  s_hh);
    cudaGetSymbolAddress((void**)&qkv, s_qkv);
    cudaGetSymbolAddress((void**)&qh,  s_qh);
    cudaGetSymbolAddress((void**)&kv,  s_kv);
    cudaGetSymbolAddress((void**)&ph,  s_ph);
    cudaGetSymbolAddress((void**)&abh, s_abh);
    cudaGetSymbolAddress((void**)&ffh, s_ffh);
    cudaGetSymbolAddress((void**)&mh,  s_mh);
    cudaGetSymbolAddress((void**)&w3,  s_w3);
    cudaGetSymbolAddress((void**)&wow, s_wow);
    cudaGetSymbolAddress((void**)&cq,  s_cq);
    cudaGetSymbolAddress((void**)&ckv, s_ckv);
    cudaGetSymbolAddress((void**)&cow, s_cow);
    cudaGetSymbolAddress((void**)&wf1, s_w1);
    cudaGetSymbolAddress((void**)&wf2, s_w2);
    cudaGetSymbolAddress((void**)&sb,  g_s);

    cudaFuncSetAttribute(gemm_tc<1, 2, 3, 0>, cudaFuncAttributeMaxDynamicSharedMemorySize, SMEMSZ);
    cudaFuncSetAttribute(gemm_tc<1, 0, 3, 0>, cudaFuncAttributeMaxDynamicSharedMemorySize, SMEMSZ);
    cudaFuncSetAttribute(gemm_tc<1, 0, 0, 0>, cudaFuncAttributeMaxDynamicSharedMemorySize, SMEMSZ);
    cudaFuncSetAttribute(gemm_tc<1, 0, 0, 2>, cudaFuncAttributeMaxDynamicSharedMemorySize, SMEMSZ);
    cudaFuncSetAttribute(gemm_tc<0, 0, 3, 0>, cudaFuncAttributeMaxDynamicSharedMemorySize, SMEMSZ);
    cudaFuncSetAttribute(gemm_tc<0, 0, 3, 1>, cudaFuncAttributeMaxDynamicSharedMemorySize, SMEMSZ);
    cudaFuncSetAttribute(gemm_tc<1, 1, 3, 0>, cudaFuncAttributeMaxDynamicSharedMemorySize, SMEMSZ);

    // One-time side-stream + events (host infra; captured work identical).
    static cudaStream_t s1 = nullptr;
    static cudaEvent_t eFork = nullptr, eJoin = nullptr;
    if (!s1) {
        cudaStreamCreateWithFlags(&s1, cudaStreamNonBlocking);
        cudaEventCreateWithFlags(&eFork, cudaEventDisableTiming);
        cudaEventCreateWithFlags(&eJoin, cudaEventDisableTiming);
    }

    const float scale = 1.0f / 32.0f;
    const long long SBATCH = (long long)LQ * SK;
    const long long nW1 = (long long)EE * EE / 4;
    const long long nFF = (long long)FFD * EE / 4;
    const long long nM  = (long long)MTOK * EE / 4;

#define CVT(st, src, dst, n4) cvt_kernel<<<(unsigned)((n4) / 256), 256, 0, st>>>(src, dst, n4)

    dim3 gQKV(3 * EE / 256, MTOK / 128);    // (12, 64)
    dim3 gKV(2 * EE / 256, MTOK / 128);     // (8, 64)
    dim3 gProj(EE / 256, MTOK / 128);       // (4, 64)
    dim3 gScore(SK / 256, LQ / 128, NB);    // (8, 16, 4)
    dim3 gPV(EE / 256, LQ / 128, NB);       // (4, 16, 4)
    dim3 gFF1(FFD / 256, MTOK / 128);       // (16, 64)

    // ---- fork: side stream does cross-attn prep + MLP weight cvts ----
    cudaEventRecord(eFork, 0);
    cudaStreamWaitEvent(s1, eFork, 0);
    CVT(s1, memory, mh, nM);
    CVT(s1, ca_kw, ckv,                   nW1);
    CVT(s1, ca_vw, ckv + (size_t)EE * EE, nW1);
    CVT(s1, ca_qw, cq,                    nW1);
    CVT(s1, ca_ow, cow,                   nW1);
    // cross kv[MTOK, 2E] = mh @ CKV^T + ca_b[E..3E)  (independent of self-attn)
    gemm_tc<1, 0, 3, 0><<<gKV, 256, SMEMSZ, s1>>>(mh, ckv, ca_b + EE, nullptr,
        nullptr, kv, EE, EE, EE, 2 * EE, 0, 0, 0, 1.f);
    CVT(s1, w1, wf1, nFF);
    CVT(s1, w2, wf2, nFF);
    cudaEventRecord(eJoin, s1);

    // ---- main stream: self-attention chain ----
    ln_kernel<<<MTOK, 256>>>(tgt, ln1_g, ln1_b, hh);
    CVT(0, sa_qw, w3,                       nW1);
    CVT(0, sa_kw, w3 + (size_t)EE * EE,     nW1);
    CVT(0, sa_vw, w3 + (size_t)2 * EE * EE, nW1);
    CVT(0, sa_ow, wow,                      nW1);
    // qkv[MTOK, 3E] = hh @ W3^T + sa_b, q-cols scaled
    gemm_tc<1, 2, 3, 0><<<gQKV, 256, SMEMSZ>>>(hh, w3, sa_b, nullptr,
        nullptr, qkv, EE, EE, EE, 3 * EE, 0, 0, 0, scale);
    // causal scores: q = qkv(+0), k = qkv(+E)
    gemm_tc<1, 0, 0, 2><<<gScore, 256, SMEMSZ>>>(qkv, qkv + EE, nullptr, nullptr,
        sb, nullptr, EE, NB * 3 * EE, NB * 3 * EE, SK, 3 * EE, 3 * EE, SBATCH, 1.f);
    softmax_kernel<<<NB * LQ, 256>>>(sb, mask, ph);
    // causal P@V (LPT order): v = qkv(+2E)
    gemm_tc<0, 0, 3, 1><<<gPV, 256, SMEMSZ>>>(ph, qkv + 2 * EE, nullptr, nullptr,
        nullptr, abh, SK, SK, NB * 3 * EE, NB * EE, SBATCH, 3 * EE, EE, 1.f);
    // x = tgt + attn @ ow^T + ob
    gemm_tc<1, 0, 0, 0><<<gProj, 256, SMEMSZ>>>(abh, wow, sa_ob, tgt,
        x, nullptr, EE, EE, EE, EE, 0, 0, 0, 1.f);

    // ---------------- cross-attention ----------------
    ln_kernel<<<MTOK, 256>>>(x, ln2_g, ln2_b, hh);
    cudaStreamWaitEvent(0, eJoin, 0);   // join: cq/kv/cow/wf1/wf2 ready
    gemm_tc<1, 0, 3, 0><<<gProj, 256, SMEMSZ>>>(hh, cq, ca_b, nullptr,
        nullptr, qh, EE, EE, EE, EE, 0, 0, 0, scale);
    gemm_tc<1, 0, 0, 0><<<gScore, 256, SMEMSZ>>>(qh, kv, nullptr, nullptr,
        sb, nullptr, EE, NB * EE, NB * 2 * EE, SK, EE, 2 * EE, SBATCH, 1.f);
    softmax_kernel<<<NB * LQ, 256>>>(sb, nullptr, ph);
    gemm_tc<0, 0, 3, 0><<<gPV, 256, SMEMSZ>>>(ph, kv + EE, nullptr, nullptr,
        nullptr, abh, SK, SK, NB * 2 * EE, NB * EE, SBATCH, 2 * EE, EE, 1.f);
    gemm_tc<1, 0, 0, 0><<<gProj, 256, SMEMSZ>>>(abh, cow, ca_ob, x,
        x, nullptr, EE, EE, EE, EE, 0, 0, 0, 1.f);

    // ---------------- MLP ----------------
    ln_kernel<<<MTOK, 256>>>(x, ln3_g, ln3_b, hh);
    gemm_tc<1, 1, 3, 0><<<gFF1, 256, SMEMSZ>>>(hh, wf1, b1, nullptr,
        nullptr, ffh, EE, EE, EE, FFD, 0, 0, 0, 1.f);
    gemm_tc<1, 0, 0, 0><<<gProj, 256, SMEMSZ>>>(ffh, wf2, b2, x,
        x, nullptr, FFD, FFD, FFD, EE, 0, 0, 0, 1.f);
#undef CVT
}

// round 15
// speedup vs baseline: 1.2752x; 1.2752x over previous
#include <cuda_runtime.h>
#include <cuda_fp16.h>
#include <math.h>
#include <stdint.h>

#define LQ   2048
#define SK   2048
#define NB   4
#define EE   1024
#define FFD  4096
#define MTOK (LQ * NB)

typedef __half  f16;
typedef __half2 f162;

// ---------------------------------------------------------------------------
// Scratch (device globals)
// ---------------------------------------------------------------------------
__device__ f16 s_hh [(size_t)MTOK * EE];          // LN out
__device__ f16 s_qkv[(size_t)MTOK * 3 * EE];      // self q|k|v fused
__device__ f16 s_qh [(size_t)MTOK * EE];          // cross q
__device__ f16 s_kv [(size_t)MTOK * 2 * EE];      // cross k|v fused
__device__ f16 s_ph [(size_t)NB * LQ * SK];       // probs
__device__ f16 s_abh[(size_t)MTOK * EE];          // attn out
__device__ f16 s_ffh[(size_t)MTOK * FFD];         // MLP hidden
__device__ f16 s_mh [(size_t)MTOK * EE];          // memory fp16
__device__ f16 s_w3 [(size_t)3 * EE * EE];        // sa qkv weights
__device__ f16 s_wow[(size_t)EE * EE];            // sa out w
__device__ f16 s_cq [(size_t)EE * EE];            // ca q w
__device__ f16 s_ckv[(size_t)2 * EE * EE];        // ca kv weights
__device__ f16 s_cow[(size_t)EE * EE];            // ca out w
__device__ f16 s_w1 [(size_t)FFD * EE];
__device__ f16 s_w2 [(size_t)FFD * EE];
__device__ float g_s [(size_t)NB * LQ * SK];      // f32 scores

// ---------------------------------------------------------------------------
// Helpers
// ---------------------------------------------------------------------------
__device__ __forceinline__ float warpSum(float v) {
#pragma unroll
    for (int o = 16; o > 0; o >>= 1) v += __shfl_xor_sync(0xffffffffu, v, o);
    return v;
}
__device__ __forceinline__ float warpMax(float v) {
#pragma unroll
    for (int o = 16; o > 0; o >>= 1) v = fmaxf(v, __shfl_xor_sync(0xffffffffu, v, o));
    return v;
}
__device__ __forceinline__ float blockSum(float v, float* sh) {
    int lane = threadIdx.x & 31, wid = threadIdx.x >> 5;
    v = warpSum(v);
    if (lane == 0) sh[wid] = v;
    __syncthreads();
    float r = (lane < 8) ? sh[lane] : 0.f;
    r = warpSum(r);
    __syncthreads();
    return r;
}
__device__ __forceinline__ float blockMax(float v, float* sh) {
    int lane = threadIdx.x & 31, wid = threadIdx.x >> 5;
    v = warpMax(v);
    if (lane == 0) sh[wid] = v;
    __syncthreads();
    float r = (lane < 8) ? sh[lane] : -3.4e38f;
    r = warpMax(r);
    __syncthreads();
    return r;
}

// ---------------------------------------------------------------------------
// PTX wrappers (sm_80-class — compute_103-safe)
// ---------------------------------------------------------------------------
__device__ __forceinline__ void cpa16(uint32_t dst, const void* src) {
    asm volatile("cp.async.cg.shared.global [%0], [%1], 16;" :: "r"(dst), "l"(src));
}
#define CP_COMMIT() asm volatile("cp.async.commit_group;" ::: "memory")
#define CP_WAIT0()  asm volatile("cp.async.wait_group 0;" ::: "memory")
#define CP_WAIT1()  asm volatile("cp.async.wait_group 1;" ::: "memory")

__device__ __forceinline__ void ldsm4(uint32_t* r, uint32_t addr) {
    asm volatile("ldmatrix.sync.aligned.m8n8.x4.shared.b16 {%0,%1,%2,%3}, [%4];"
        : "=r"(r[0]), "=r"(r[1]), "=r"(r[2]), "=r"(r[3]) : "r"(addr));
}
__device__ __forceinline__ void ldsm2(uint32_t* r, uint32_t addr) {
    asm volatile("ldmatrix.sync.aligned.m8n8.x2.shared.b16 {%0,%1}, [%2];"
        : "=r"(r[0]), "=r"(r[1]) : "r"(addr));
}
__device__ __forceinline__ void ldsm2t(uint32_t* r, uint32_t addr) {
    asm volatile("ldmatrix.sync.aligned.m8n8.x2.trans.shared.b16 {%0,%1}, [%2];"
        : "=r"(r[0]), "=r"(r[1]) : "r"(addr));
}
__device__ __forceinline__ void mma_f16(float* d, const uint32_t* a, const uint32_t* b) {
    asm volatile(
        "mma.sync.aligned.m16n8k16.row.col.f32.f16.f16.f32 "
        "{%0,%1,%2,%3}, {%4,%5,%6,%7}, {%8,%9}, {%0,%1,%2,%3};\n"
        : "+f"(d[0]), "+f"(d[1]), "+f"(d[2]), "+f"(d[3])
        : "r"(a[0]), "r"(a[1]), "r"(a[2]), "r"(a[3]), "r"(b[0]), "r"(b[1]));
}

// ---------------------------------------------------------------------------
// f32 -> fp16 convert
// ---------------------------------------------------------------------------
__global__ void cvt_kernel(const float* __restrict__ x, f16* __restrict__ o,
                           long long n4) {
    long long i = blockIdx.x * (long long)blockDim.x + threadIdx.x;
    if (i >= n4) return;
    float4 v = ((const float4*)x)[i];
    ((f162*)o)[i * 2]     = __halves2half2(__float2half_rn(v.x), __float2half_rn(v.y));
    ((f162*)o)[i * 2 + 1] = __halves2half2(__float2half_rn(v.z), __float2half_rn(v.w));
}

// ---------------------------------------------------------------------------
// LayerNorm -> fp16
// ---------------------------------------------------------------------------
__global__ void ln_kernel(const float* __restrict__ x, const float* __restrict__ g,
                          const float* __restrict__ b, f16* __restrict__ oh) {
    __shared__ float sh[32];
    long long row = blockIdx.x;
    float4 v = ((const float4*)(x + row * EE))[threadIdx.x];
    float s  = v.x + v.y + v.z + v.w;
    float sq = v.x * v.x + v.y * v.y + v.z * v.z + v.w * v.w;
    s  = blockSum(s,  sh);
    sq = blockSum(sq, sh);
    float mean = s * (1.f / EE);
    float var  = sq * (1.f / EE) - mean * mean;
    float inv  = rsqrtf(var + 1e-5f);
    float4 gv = ((const float4*)g)[threadIdx.x];
    float4 bv = ((const float4*)b)[threadIdx.x];
    float o0 = (v.x - mean) * inv * gv.x + bv.x;
    float o1 = (v.y - mean) * inv * gv.y + bv.y;
    float o2 = (v.z - mean) * inv * gv.z + bv.z;
    float o3 = (v.w - mean) * inv * gv.w + bv.w;
    f162* ph = (f162*)(oh + row * EE);
    ph[threadIdx.x * 2]     = __halves2half2(__float2half_rn(o0), __float2half_rn(o1));
    ph[threadIdx.x * 2 + 1] = __halves2half2(__float2half_rn(o2), __float2half_rn(o3));
}

// ---------------------------------------------------------------------------
// Softmax over S=2048 -> fp16 probs; mask-select (skipped tiles never read).
// Causal rows skip loading the second half when fully masked.
// ---------------------------------------------------------------------------
__global__ void softmax_kernel(const float* __restrict__ s, const float* __restrict__ mask,
                               f16* __restrict__ oh) {
    __shared__ float sh[32];
    long long row = blockIdx.x;
    int l = (int)(row & (LQ - 1));
    const float4* sr = (const float4*)(s + row * (long long)SK);
    float4 va = sr[threadIdx.x];
    float4 vb;
    bool need_b = !mask || (1024 + (int)threadIdx.x * 4 <= l);
    if (need_b) vb = sr[threadIdx.x + 256];
    else        vb = make_float4(-3.0e38f, -3.0e38f, -3.0e38f, -3.0e38f);
    if (mask) {
        const float4* mr = (const float4*)(mask + (long long)l * SK);
        float4 ma = mr[threadIdx.x];
        va.x = (ma.x < -1e8f) ? -3.0e38f : va.x;
        va.y = (ma.y < -1e8f) ? -3.0e38f : va.y;
        va.z = (ma.z < -1e8f) ? -3.0e38f : va.z;
        va.w = (ma.w < -1e8f) ? -3.0e38f : va.w;
        if (need_b) {
            float4 mb = mr[threadIdx.x + 256];
            vb.x = (mb.x < -1e8f) ? -3.0e38f : vb.x;
            vb.y = (mb.y < -1e8f) ? -3.0e38f : vb.y;
            vb.z = (mb.z < -1e8f) ? -3.0e38f : vb.z;
            vb.w = (mb.w < -1e8f) ? -3.0e38f : vb.w;
        }
    }
    float mx = fmaxf(fmaxf(fmaxf(va.x, va.y), fmaxf(va.z, va.w)),
                     fmaxf(fmaxf(vb.x, vb.y), fmaxf(vb.z, vb.w)));
    mx = blockMax(mx, sh);
    va.x = __expf(va.x - mx); va.y = __expf(va.y - mx);
    va.z = __expf(va.z - mx); va.w = __expf(va.w - mx);
    vb.x = __expf(vb.x - mx); vb.y = __expf(vb.y - mx);
    vb.z = __expf(vb.z - mx); vb.w = __expf(vb.w - mx);
    float sum = va.x + va.y + va.z + va.w + vb.x + vb.y + vb.z + vb.w;
    sum = blockSum(sum, sh);
    float inv = 1.f / sum;
    f162* ph = (f162*)(oh + row * (long long)SK);
    ph[threadIdx.x * 2] = __halves2half2(__float2half_rn(va.x * inv), __float2half_rn(va.y * inv));
    ph[threadIdx.x * 2 + 1] = __halves2half2(__float2half_rn(va.z * inv), __float2half_rn(va.w * inv));
    ph[(threadIdx.x + 256) * 2] = __halves2half2(__float2half_rn(vb.x * inv), __float2half_rn(vb.y * inv));
    ph[(threadIdx.x + 256) * 2 + 1] = __halves2half2(__float2half_rn(vb.z * inv), __float2half_rn(vb.w * inv));
}

// ---------------------------------------------------------------------------
// Tensor-core GEMM, single-term fp16: C = epi(A @ op(B)).
// 128x128 CTA tile, BK=64, 256 threads (2x4 warps), 64x32 warp tile.
// 3-stage cp.async pipeline, one __syncthreads per 64-K step, 2 CTA/SM.
// TRANSB=1: B [N,K] row-major. TRANSB=0: B [K,N].
// ACT: 0 none, 1 QuickGELU, 2 = alpha applied only to cols < EE (fused QKV).
// OUT: 0 = f32 (+res), 3 = fp16.
// CAUSAL: 0 none, 1 = K truncated at bm+128 (P@V, LPT-reversed bm order),
//         2 = skip tiles bn>bm.
// smem/stage: A 128x144B = 18432, B 128x144B (or 64x272B=17408) -> 36864.
// ---------------------------------------------------------------------------
#define A_STRIDE 144u
#define B_OFF    18432u
#define STAGE    36864u
#define SMEMSZ   (3u * STAGE)

template <int TRANSB, int ACT, int OUT, int CAUSAL>
__global__ void __launch_bounds__(256, 2)
gemm_tc(const f16* __restrict__ Ah, const f16* __restrict__ Bh,
        const float* __restrict__ bias, const float* __restrict__ res,
        float* C, f16* Ch,
        int K, int lda, int ldb, int ldc,
        long long sA, long long sB, long long sC, float alpha) {
    // LPT: for variable-K causal P@V, schedule longest-K CTAs first.
    const int ytile = (CAUSAL == 1) ? (gridDim.y - 1 - blockIdx.y) : blockIdx.y;
    const int bm = ytile * 128;
    const int bn = blockIdx.x * 128;
    if (CAUSAL == 2 && bn > bm) return;     // fully-masked score tile

    Ah += (long long)blockIdx.z * sA;
    Bh += (long long)blockIdx.z * sB;
    if (OUT == 0) { C  += (long long)blockIdx.z * sC; if (res) res += (long long)blockIdx.z * sC; }
    else          { Ch += (long long)blockIdx.z * sC; }

    extern __shared__ f16 smem[];
    const uint32_t sbase = (uint32_t)__cvta_generic_to_shared(smem);
    const int tid  = threadIdx.x;
    const int lane = tid & 31;
    const int warp = tid >> 5;
    const int wm = warp >> 2;   // 0..1
    const int wn = warp & 3;    // 0..3

    float acc[4][4][4];
#pragma unroll
    for (int i = 0; i < 4; i++)
#pragma unroll
        for (int j = 0; j < 4; j++)
#pragma unroll
            for (int q = 0; q < 4; q++) acc[i][j][q] = 0.f;

    auto load_stage = [&](int st, int k0) {
        uint32_t sb = sbase + (uint32_t)st * STAGE;
#pragma unroll
        for (int i = 0; i < 4; i++) {               // A: 128 rows x 8 16B chunks
            int c = tid + i * 256;
            int row = c >> 3, kc = c & 7;
            size_t off = (size_t)(bm + row) * lda + k0 + kc * 8;
            cpa16(sb + row * A_STRIDE + kc * 16, Ah + off);
        }
        if (TRANSB) {
#pragma unroll
            for (int i = 0; i < 4; i++) {           // B: 128 rows x 8 chunks
                int c = tid + i * 256;
                int row = c >> 3, kc = c & 7;
                size_t off = (size_t)(bn + row) * ldb + k0 + kc * 8;
                cpa16(sb + B_OFF + row * A_STRIDE + kc * 16, Bh + off);
            }
        } else {
#pragma unroll
            for (int i = 0; i < 4; i++) {           // B: 64 k-rows x 16 chunks
                int c = tid + i * 256;
                int row = c >> 4, nc = c & 15;
                size_t off = (size_t)(k0 + row) * ldb + bn + nc * 8;
                cpa16(sb + B_OFF + row * 272 + nc * 16, Bh + off);
            }
        }
        CP_COMMIT();
    };

    auto compute_stage = [&](int st) {
        uint32_t sA_ = sbase + (uint32_t)st * STAGE;
        uint32_t sB_ = sA_ + B_OFF;
#pragma unroll
        for (int ks = 0; ks < 4; ks++) {
            const int k16 = ks * 16;
            uint32_t ah[4][4], bh[4][2];
            const int arow = lane & 15;
            const int acol = k16 + (lane >> 4) * 8;
#pragma unroll
            for (int mt = 0; mt < 4; mt++) {
                uint32_t addr = sA_ + (uint32_t)((wm * 64 + mt * 16 + arow) * A_STRIDE + acol * 2);
                ldsm4(ah[mt], addr);
            }
            if (TRANSB) {
                const int brow = lane & 7;
                const int bk   = k16 + ((lane >> 3) & 1) * 8;
#pragma unroll
                for (int nt = 0; nt < 4; nt++) {
                    uint32_t addr = sB_ + (uint32_t)((wn * 32 + nt * 8 + brow) * A_STRIDE + bk * 2);
                    ldsm2(bh[nt], addr);
                }
            } else {
                const int brow = k16 + (lane & 15);
#pragma unroll
                for (int nt = 0; nt < 4; nt++) {
                    uint32_t addr = sB_ + (uint32_t)(brow * 272 + (wn * 32 + nt * 8) * 2);
                    ldsm2t(bh[nt], addr);
                }
            }
#pragma unroll
            for (int mt = 0; mt < 4; mt++)
#pragma unroll
                for (int nt = 0; nt < 4; nt++)
                    mma_f16(acc[mt][nt], ah[mt], bh[nt]);
        }
    };

    const int Kend = (CAUSAL == 1) ? min(K, bm + 128) : K;
    const int KT = Kend >> 6;   // K / 64
    load_stage(0, 0);
    if (KT > 1) load_stage(1, 64);
    for (int kt = 0; kt < KT; kt++) {
        if (kt + 1 < KT) CP_WAIT1(); else CP_WAIT0();
        __syncthreads();
        if (kt + 2 < KT) load_stage((kt + 2) % 3, (kt + 2) * 64);
        compute_stage(kt % 3);
    }

    // Epilogue
#pragma unroll
    for (int mt = 0; mt < 4; mt++) {
        const int r0 = bm + wm * 64 + mt * 16 + (lane >> 2);
#pragma unroll
        for (int nt = 0; nt < 4; nt++) {
            const int c = bn + wn * 32 + nt * 8 + (lane & 3) * 2;
            float bc0 = 0.f, bc1 = 0.f;
            if (bias) { bc0 = bias[c]; bc1 = bias[c + 1]; }
            const float af = (ACT == 2) ? ((c < EE) ? alpha : 1.f) : alpha;
#pragma unroll
            for (int h = 0; h < 2; h++) {
                float v0 = acc[mt][nt][h * 2 + 0] + bc0;
                float v1 = acc[mt][nt][h * 2 + 1] + bc1;
                v0 *= af; v1 *= af;
                if (ACT == 1) {
                    v0 = v0 / (1.f + __expf(-1.702f * v0));
                    v1 = v1 / (1.f + __expf(-1.702f * v1));
                }
                const size_t row = (size_t)(r0 + h * 8);
                if (OUT == 0) {
                    if (res) {
                        const float2 rv = *(const float2*)(res + row * ldc + c);
                        v0 += rv.x; v1 += rv.y;
                    }
                    *(float2*)(C + row * ldc + c) = make_float2(v0, v1);
                } else {
                    *(f162*)(Ch + row * ldc + c) =
                        __halves2half2(__float2half_rn(v0), __float2half_rn(v1));
                }
            }
        }
    }
}

// ---------------------------------------------------------------------------
// Host launcher — R13 dual-stream fork-join topology (known-good)
// ---------------------------------------------------------------------------
extern "C" void kernel_launch(void* const* d_in, const int* in_sizes, int n_in,
                              void* d_out, int out_size) {
    const float* tgt    = (const float*)d_in[0];
    const float* memory = (const float*)d_in[1];
    const float* mask   = (const float*)d_in[2];
    const float* sa_qw  = (const float*)d_in[3];
    const float* sa_kw  = (const float*)d_in[4];
    const float* sa_vw  = (const float*)d_in[5];
    const float* sa_b   = (const float*)d_in[6];
    const float* sa_ow  = (const float*)d_in[7];
    const float* sa_ob  = (const float*)d_in[8];
    const float* ca_qw  = (const float*)d_in[9];
    const float* ca_kw  = (const float*)d_in[10];
    const float* ca_vw  = (const float*)d_in[11];
    const float* ca_b   = (const float*)d_in[12];
    const float* ca_ow  = (const float*)d_in[13];
    const float* ca_ob  = (const float*)d_in[14];
    const float* ln1_g  = (const float*)d_in[15];
    const float* ln1_b  = (const float*)d_in[16];
    const float* ln2_g  = (const float*)d_in[17];
    const float* ln2_b  = (const float*)d_in[18];
    const float* ln3_g  = (const float*)d_in[19];
    const float* ln3_b  = (const float*)d_in[20];
    const float* w1     = (const float*)d_in[21];
    const float* b1     = (const float*)d_in[22];
    const float* w2     = (const float*)d_in[23];
    const float* b2     = (const float*)d_in[24];
    float* x = (float*)d_out;

    f16 *hh, *qkv, *qh, *kv, *ph, *abh, *ffh, *mh, *w3, *wow, *cq, *ckv, *cow, *wf1, *wf2;
    float* sb;
    cudaGetSymbolAddress((void**)&hh,  s_hh);
    cudaGetSymbolAddress((void**)&qkv, s_qkv);
    cudaGetSymbolAddress((void**)&qh,  s_qh);
    cudaGetSymbolAddress((void**)&kv,  s_kv);
    cudaGetSymbolAddress((void**)&ph,  s_ph);
    cudaGetSymbolAddress((void**)&abh, s_abh);
    cudaGetSymbolAddress((void**)&ffh, s_ffh);
    cudaGetSymbolAddress((void**)&mh,  s_mh);
    cudaGetSymbolAddress((void**)&w3,  s_w3);
    cudaGetSymbolAddress((void**)&wow, s_wow);
    cudaGetSymbolAddress((void**)&cq,  s_cq);
    cudaGetSymbolAddress((void**)&ckv, s_ckv);
    cudaGetSymbolAddress((void**)&cow, s_cow);
    cudaGetSymbolAddress((void**)&wf1, s_w1);
    cudaGetSymbolAddress((void**)&wf2, s_w2);
    cudaGetSymbolAddress((void**)&sb,  g_s);

    cudaFuncSetAttribute(gemm_tc<1, 2, 3, 0>, cudaFuncAttributeMaxDynamicSharedMemorySize, SMEMSZ);
    cudaFuncSetAttribute(gemm_tc<1, 0, 3, 0>, cudaFuncAttributeMaxDynamicSharedMemorySize, SMEMSZ);
    cudaFuncSetAttribute(gemm_tc<1, 0, 0, 0>, cudaFuncAttributeMaxDynamicSharedMemorySize, SMEMSZ);
    cudaFuncSetAttribute(gemm_tc<1, 0, 0, 2>, cudaFuncAttributeMaxDynamicSharedMemorySize, SMEMSZ);
    cudaFuncSetAttribute(gemm_tc<0, 0, 3, 0>, cudaFuncAttributeMaxDynamicSharedMemorySize, SMEMSZ);
    cudaFuncSetAttribute(gemm_tc<0, 0, 3, 1>, cudaFuncAttributeMaxDynamicSharedMemorySize, SMEMSZ);
    cudaFuncSetAttribute(gemm_tc<1, 1, 3, 0>, cudaFuncAttributeMaxDynamicSharedMemorySize, SMEMSZ);

    // One-time side-stream + events (host infra; captured work identical).
    static cudaStream_t s1 = nullptr;
    static cudaEvent_t eFork = nullptr, eJoin = nullptr;
    if (!s1) {
        cudaStreamCreateWithFlags(&s1, cudaStreamNonBlocking);
        cudaEventCreateWithFlags(&eFork, cudaEventDisableTiming);
        cudaEventCreateWithFlags(&eJoin, cudaEventDisableTiming);
    }

    const float scale = 1.0f / 32.0f;
    const long long SBATCH = (long long)LQ * SK;
    const long long nW1 = (long long)EE * EE / 4;
    const long long nFF = (long long)FFD * EE / 4;
    const long long nM  = (long long)MTOK * EE / 4;

#define CVT(st, src, dst, n4) cvt_kernel<<<(unsigned)((n4) / 256), 256, 0, st>>>(src, dst, n4)

    dim3 gQKV(3 * EE / 128, MTOK / 128);    // (24, 64)
    dim3 gKV(2 * EE / 128, MTOK / 128);     // (16, 64)
    dim3 gProj(EE / 128, MTOK / 128);       // (8, 64)
    dim3 gScore(SK / 128, LQ / 128, NB);    // (16, 16, 4)
    dim3 gPV(EE / 128, LQ / 128, NB);       // (8, 16, 4)
    dim3 gFF1(FFD / 128, MTOK / 128);       // (32, 64)

    // ---- fork: side stream does cross-attn prep + MLP weight cvts ----
    cudaEventRecord(eFork, 0);
    cudaStreamWaitEvent(s1, eFork, 0);
    CVT(s1, memory, mh, nM);
    CVT(s1, ca_kw, ckv,                   nW1);
    CVT(s1, ca_vw, ckv + (size_t)EE * EE, nW1);
    CVT(s1, ca_qw, cq,                    nW1);
    CVT(s1, ca_ow, cow,                   nW1);
    // cross kv[MTOK, 2E] = mh @ CKV^T + ca_b[E..3E)  (independent of self-attn)
    gemm_tc<1, 0, 3, 0><<<gKV, 256, SMEMSZ, s1>>>(mh, ckv, ca_b + EE, nullptr,
        nullptr, kv, EE, EE, EE, 2 * EE, 0, 0, 0, 1.f);
    CVT(s1, w1, wf1, nFF);
    CVT(s1, w2, wf2, nFF);
    cudaEventRecord(eJoin, s1);

    // ---- main stream: self-attention chain ----
    ln_kernel<<<MTOK, 256>>>(tgt, ln1_g, ln1_b, hh);
    CVT(0, sa_qw, w3,                       nW1);
    CVT(0, sa_kw, w3 + (size_t)EE * EE,     nW1);
    CVT(0, sa_vw, w3 + (size_t)2 * EE * EE, nW1);
    CVT(0, sa_ow, wow,                      nW1);
    // qkv[MTOK, 3E] = hh @ W3^T + sa_b, q-cols scaled
    gemm_tc<1, 2, 3, 0><<<gQKV, 256, SMEMSZ>>>(hh, w3, sa_b, nullptr,
        nullptr, qkv, EE, EE, EE, 3 * EE, 0, 0, 0, scale);
    // causal scores: q = qkv(+0), k = qkv(+E)
    gemm_tc<1, 0, 0, 2><<<gScore, 256, SMEMSZ>>>(qkv, qkv + EE, nullptr, nullptr,
        sb, nullptr, EE, NB * 3 * EE, NB * 3 * EE, SK, 3 * EE, 3 * EE, SBATCH, 1.f);
    softmax_kernel<<<NB * LQ, 256>>>(sb, mask, ph);
    // causal P@V (LPT order): v = qkv(+2E)
    gemm_tc<0, 0, 3, 1><<<gPV, 256, SMEMSZ>>>(ph, qkv + 2 * EE, nullptr, nullptr,
        nullptr, abh, SK, SK, NB * 3 * EE, NB * EE, SBATCH, 3 * EE, EE, 1.f);
    // x = tgt + attn @ ow^T + ob
    gemm_tc<1, 0, 0, 0><<<gProj, 256, SMEMSZ>>>(abh, wow, sa_ob, tgt,
        x, nullptr, EE, EE, EE, EE, 0, 0, 0, 1.f);

    // ---------------- cross-attention ----------------
    ln_kernel<<<MTOK, 256>>>(x, ln2_g, ln2_b, hh);
    cudaStreamWaitEvent(0, eJoin, 0);   // join: cq/kv/cow/wf1/wf2 ready
    gemm_tc<1, 0, 3, 0><<<gProj, 256, SMEMSZ>>>(hh, cq, ca_b, nullptr,
        nullptr, qh, EE, EE, EE, EE, 0, 0, 0, scale);
    gemm_tc<1, 0, 0, 0><<<gScore, 256, SMEMSZ>>>(qh, kv, nullptr, nullptr,
        sb, nullptr, EE, NB * EE, NB * 2 * EE, SK, EE, 2 * EE, SBATCH, 1.f);
    softmax_kernel<<<NB * LQ, 256>>>(sb, nullptr, ph);
    gemm_tc<0, 0, 3, 0><<<gPV, 256, SMEMSZ>>>(ph, kv + EE, nullptr, nullptr,
        nullptr, abh, SK, SK, NB * 2 * EE, NB * EE, SBATCH, 2 * EE, EE, 1.f);
    gemm_tc<1, 0, 0, 0><<<gProj, 256, SMEMSZ>>>(abh, cow, ca_ob, x,
        x, nullptr, EE, EE, EE, EE, 0, 0, 0, 1.f);

    // ---------------- MLP ----------------
    ln_kernel<<<MTOK, 256>>>(x, ln3_g, ln3_b, hh);
    gemm_tc<1, 1, 3, 0><<<gFF1, 256, SMEMSZ>>>(hh, wf1, b1, nullptr,
        nullptr, ffh, EE, EE, EE, FFD, 0, 0, 0, 1.f);
    gemm_tc<1, 0, 0, 0><<<gProj, 256, SMEMSZ>>>(ffh, wf2, b2, x,
        x, nullptr, FFD, FFD, FFD, EE, 0, 0, 0, 1.f);
#undef CVT
}